// round 7
// baseline (speedup 1.0000x reference)
#include <cuda_runtime.h>
#include <cuda_fp16.h>
#include <cstdint>

// ============================================================
// Problem: out[B,256] = relu(X[B,1024] @ W^T + c)
//   X = [text | image], W/c precomputed from small weights.
//   B = 65536, H = 256, K = 1024.
// ============================================================
#define HDIM 256
#define KTOT 1024

// ---------------- device scratch ----------------
__device__ float  g_M1[HDIM * HDIM];
__device__ float  g_G1[HDIM * HDIM];
__device__ float  g_G2[HDIM * HDIM];
__device__ __half g_W16[HDIM * KTOT];   // fused weight, fp16, [256 rows][1024 k]
__device__ float  g_b1[HDIM];
__device__ float  g_c[HDIM];

// ---------------- PTX helpers ----------------
__device__ __forceinline__ uint32_t smem_u32(const void* p) {
    uint32_t a;
    asm("{ .reg .u64 t; cvta.to.shared.u64 t, %1; cvt.u32.u64 %0, t; }"
        : "=r"(a) : "l"(p));
    return a;
}

#define SW(x) ((x) ^ (((x) >> 3) & 0x70))

#define LDSM_X4(r0, r1, r2, r3, addr) \
    asm volatile("ldmatrix.sync.aligned.m8n8.x4.shared.b16 {%0,%1,%2,%3}, [%4];\n" \
        : "=r"(r0), "=r"(r1), "=r"(r2), "=r"(r3) : "r"(addr))

#define MMA16816(d, a, b0_, b1_) \
    asm volatile("mma.sync.aligned.m16n8k16.row.col.f32.f16.f16.f32 " \
        "{%0,%1,%2,%3}, {%4,%5,%6,%7}, {%8,%9}, {%0,%1,%2,%3};\n" \
        : "+f"((d)[0]), "+f"((d)[1]), "+f"((d)[2]), "+f"((d)[3]) \
        : "r"((a)[0]), "r"((a)[1]), "r"((a)[2]), "r"((a)[3]), "r"(b0_), "r"(b1_))

#define CP_ASYNC16(dst, src) \
    asm volatile("cp.async.cg.shared.global [%0], [%1], 16;\n" :: "r"(dst), "l"(src))
#define CP_COMMIT() asm volatile("cp.async.commit_group;\n")
#define CP_WAIT0()  asm volatile("cp.async.wait_group 0;\n" ::: "memory")

// named barriers (producer/consumer)
#define BAR_SYNC(id, cnt) \
    asm volatile("bar.sync %0, %1;" :: "r"(id), "r"(cnt) : "memory")
#define BAR_ARRIVE(id, cnt) \
    asm volatile("bar.arrive %0, %1;" :: "r"(id), "r"(cnt) : "memory")

// ============================================================
// Precompute GEMMs: 64x64 tiles, 4x4 per thread, 256 threads,
// register-double-buffered K loop
// ============================================================
template<bool HALF_OUT>
__device__ __forceinline__ void gemm64_body(const float* __restrict__ A, int lda,
                                            const float* __restrict__ B, int ldb,
                                            void* __restrict__ C, int ldc, int K,
                                            int i0, int j0) {
    __shared__ float As[32][72];   // As[k][m] (transposed)
    __shared__ float Bs[32][72];   // Bs[k][n]
    const int t = threadIdx.x;
    const int tx = t & 15, ty = t >> 4;
    float acc[4][4] = {};

    // per-thread staging regs for next chunk
    float ra[8], rb[8];
    int ra_r[8], ra_c[8], rb_r[8], rb_c[8];
    #pragma unroll
    for (int u = 0; u < 8; u++) {
        int idx = t + u * 256;
        ra_r[u] = idx >> 5;  ra_c[u] = idx & 31;   // 64 rows x 32 k
        rb_r[u] = idx >> 6;  rb_c[u] = idx & 63;   // 32 k x 64 cols
    }

    // load chunk 0 into regs
    #pragma unroll
    for (int u = 0; u < 8; u++) {
        ra[u] = A[(size_t)(i0 + ra_r[u]) * lda + ra_c[u]];
        rb[u] = B[(size_t)rb_r[u] * ldb + j0 + rb_c[u]];
    }

    for (int k0 = 0; k0 < K; k0 += 32) {
        // stage current chunk
        #pragma unroll
        for (int u = 0; u < 8; u++) {
            As[ra_c[u]][ra_r[u]] = ra[u];
            Bs[rb_r[u]][rb_c[u]] = rb[u];
        }
        __syncthreads();
        // prefetch next chunk into regs (overlaps compute)
        if (k0 + 32 < K) {
            #pragma unroll
            for (int u = 0; u < 8; u++) {
                ra[u] = A[(size_t)(i0 + ra_r[u]) * lda + k0 + 32 + ra_c[u]];
                rb[u] = B[(size_t)(k0 + 32 + rb_r[u]) * ldb + j0 + rb_c[u]];
            }
        }
        #pragma unroll
        for (int k = 0; k < 32; k++) {
            float4 a4 = *(const float4*)&As[k][ty * 4];
            float4 b4 = *(const float4*)&Bs[k][tx * 4];
            acc[0][0] += a4.x * b4.x; acc[0][1] += a4.x * b4.y;
            acc[0][2] += a4.x * b4.z; acc[0][3] += a4.x * b4.w;
            acc[1][0] += a4.y * b4.x; acc[1][1] += a4.y * b4.y;
            acc[1][2] += a4.y * b4.z; acc[1][3] += a4.y * b4.w;
            acc[2][0] += a4.z * b4.x; acc[2][1] += a4.z * b4.y;
            acc[2][2] += a4.z * b4.z; acc[2][3] += a4.z * b4.w;
            acc[3][0] += a4.w * b4.x; acc[3][1] += a4.w * b4.y;
            acc[3][2] += a4.w * b4.z; acc[3][3] += a4.w * b4.w;
        }
        __syncthreads();
    }
    #pragma unroll
    for (int r = 0; r < 4; r++)
        #pragma unroll
        for (int c = 0; c < 4; c++) {
            size_t o = (size_t)(i0 + ty * 4 + r) * ldc + j0 + tx * 4 + c;
            if (HALF_OUT) ((__half*)C)[o] = __float2half_rn(acc[r][c]);
            else          ((float*)C)[o]  = acc[r][c];
        }
}

// Launch 1: z=0 -> M1 = Wo @ Wv ; z=1, block(0,0) -> b1 = Wo@bv + bo
__global__ void k_M1(const float* __restrict__ Wo, const float* __restrict__ Wv,
                     const float* __restrict__ in_proj_b,
                     const float* __restrict__ out_proj_b) {
    if (blockIdx.z == 1) {
        if (blockIdx.x | blockIdx.y) return;
        const int i = threadIdx.x;
        const float4* w  = (const float4*)(Wo + i * HDIM);
        const float4* bv = (const float4*)(in_proj_b + 2 * HDIM);
        float s = 0.f;
        #pragma unroll 8
        for (int k = 0; k < 64; k++) {
            float4 a = __ldg(&w[k]), b = __ldg(&bv[k]);
            s += a.x * b.x + a.y * b.y + a.z * b.z + a.w * b.w;
        }
        g_b1[i] = s + out_proj_b[i];
        return;
    }
    gemm64_body<false>(Wo, 256, Wv, 256, g_M1, 256, 256,
                       blockIdx.y * 64, blockIdx.x * 64);
}

// Launch 2: z=0: G1 = Wf1 @ M1 ; z=1: G2 = Wf2 @ M1
__global__ void k_G(const float* __restrict__ W_fuse) {
    const float* A = W_fuse + blockIdx.z * 256;
    float* C = blockIdx.z ? g_G2 : g_G1;
    gemm64_body<false>(A, 512, g_M1, 256, C, 256, 256,
                       blockIdx.y * 64, blockIdx.x * 64);
}

// Launch 3: z=0: W[:, :512] = G2 @ W_text ; z=1: W[:, 512:] = G1 @ W_img (fp16)
//           z=2, block(0,0): c = G1@b_img + G2@b_text + (Wf1+Wf2)@b1 + b_fuse
__global__ void k_W(const float* __restrict__ W_text, const float* __restrict__ W_img,
                    const float* __restrict__ W_fuse,
                    const float* __restrict__ b_text, const float* __restrict__ b_img,
                    const float* __restrict__ b_fuse) {
    if (blockIdx.z == 2) {
        if (blockIdx.x | blockIdx.y) return;
        const int i = threadIdx.x;
        const float4* g1 = (const float4*)(g_G1 + i * HDIM);
        const float4* g2 = (const float4*)(g_G2 + i * HDIM);
        const float4* w1 = (const float4*)(W_fuse + i * 512);
        const float4* w2 = (const float4*)(W_fuse + i * 512 + 256);
        const float4* vi = (const float4*)b_img;
        const float4* vt = (const float4*)b_text;
        const float4* v1 = (const float4*)g_b1;
        float s = b_fuse[i];
        #pragma unroll 4
        for (int k = 0; k < 64; k++) {
            float4 a = __ldg(&g1[k]), b = __ldg(&vi[k]);
            s += a.x * b.x + a.y * b.y + a.z * b.z + a.w * b.w;
            a = __ldg(&g2[k]); b = __ldg(&vt[k]);
            s += a.x * b.x + a.y * b.y + a.z * b.z + a.w * b.w;
            float4 c1 = __ldg(&w1[k]), c2 = __ldg(&w2[k]); b = v1[k];
            s += (c1.x + c2.x) * b.x + (c1.y + c2.y) * b.y
               + (c1.z + c2.z) * b.z + (c1.w + c2.w) * b.w;
        }
        g_c[i] = s;
        return;
    }
    const int z = blockIdx.z;
    const float* A = z ? g_G1 : g_G2;
    const float* B = z ? W_img : W_text;
    __half* C = g_W16 + z * 512;
    gemm64_body<true>(A, 256, B, 512, C, 1024, 256,
                      blockIdx.y * 64, blockIdx.x * 64);
}

// ============================================================
// Main GEMM, warp-specialized:
//   CTA tile 128x256, K-chunk 64, 2 smem stages.
//   Warps 0-15 (512 thr): consumers — LDSM + MMA + epilogue.
//   Warps 16-17 (64 thr):  producers — LDG A fp32 -> cvt fp16 -> STS,
//                          cp.async B, named-barrier handshake.
// Named barriers: full_s = 1+s (prod arrive, cons sync)
//                 empty_s = 3+s (cons arrive, prod sync)
// ============================================================
#define STAGE 49152                    // 16KB A + 32KB B
#define DYNSMEM (1024 + 1024 + 2 * STAGE)
#define NTHR 576

__global__ void __launch_bounds__(NTHR, 1)
fused_gemm(const float* __restrict__ text, const float* __restrict__ image,
           float* __restrict__ out) {
    extern __shared__ char smem_raw[];
    char* dsm = (char*)(((uintptr_t)smem_raw + 1023) & ~(uintptr_t)1023);
    const uint32_t sb = smem_u32(dsm);
    const int tid = threadIdx.x;
    const int lane = tid & 31;
    const int wid = tid >> 5;          // 0..17
    const int mblk = blockIdx.x;

    float* bias_s = (float*)dsm;
    if (tid < 256) bias_s[tid] = g_c[tid];   // ordered before epilogue by bar chain

    const float* srcT = text  + (size_t)mblk * 128 * 512;
    const float* srcI = image + (size_t)mblk * 128 * 512;

    if (wid >= 16) {
        // ================= producers =================
        const int ptid = tid - 512;               // 0..63
        const int a_r = ptid >> 4, a_c = ptid & 15;   // A: rows a_r + u*4
        const int b_r = ptid >> 3, b_c = ptid & 7;    // B: rows b_r + u*8
        #pragma unroll 1
        for (int kn = 0; kn < 16; kn++) {
            const int s = kn & 1;
            if (kn >= 2) BAR_SYNC(3 + s, NTHR);       // wait stage empty
            const float* src = (kn < 8) ? srcT : srcI;
            const int kl = (kn & 7) * 64;
            char* stg = dsm + 1024 + s * STAGE;
            // ---- A: 128x64 fp32 -> fp16, swizzled ----
            #pragma unroll
            for (int b0 = 0; b0 < 32; b0 += 8) {
                float4 v[8];
                #pragma unroll
                for (int j = 0; j < 8; j++) {
                    int r = a_r + (b0 + j) * 4;
                    v[j] = __ldg((const float4*)(src + (size_t)r * 512 + kl + a_c * 4));
                }
                #pragma unroll
                for (int j = 0; j < 8; j++) {
                    int r = a_r + (b0 + j) * 4;
                    uint32_t off = SW((uint32_t)(r * 128 + a_c * 8));
                    __half2 h0 = __floats2half2_rn(v[j].x, v[j].y);
                    __half2 h1 = __floats2half2_rn(v[j].z, v[j].w);
                    *(uint2*)(stg + off) = make_uint2(*(uint32_t*)&h0, *(uint32_t*)&h1);
                }
            }
            // ---- B: 256x64 fp16 via cp.async, swizzled ----
            {
                uint32_t Bb = sb + 1024 + s * STAGE + 16384;
                #pragma unroll
                for (int u = 0; u < 32; u++) {
                    int r = b_r + u * 8;
                    uint32_t dst = Bb + SW((uint32_t)(r * 128 + b_c * 16));
                    CP_ASYNC16(dst, g_W16 + (size_t)r * 1024 + kn * 64 + b_c * 8);
                }
                CP_COMMIT();
                CP_WAIT0();
            }
            BAR_ARRIVE(1 + s, NTHR);                  // signal stage full
        }
        return;   // arrivals are banked; consumers proceed
    }

    // ================= consumers =================
    const int wm = wid & 3;            // 4 m-blocks of 32
    const int wn = wid >> 2;           // 4 n-blocks of 64
    float acc[2][8][4] = {};

    const uint32_t xorv  = (uint32_t)((lane & 7) << 4);
    const int      rl    = lane & 15;
    const uint32_t khalf = (uint32_t)(((lane >> 4) & 1) * 16);

    #pragma unroll 1
    for (int kc = 0; kc < 16; kc++) {
        const int s = kc & 1;
        BAR_SYNC(1 + s, NTHR);                        // wait stage full
        const uint32_t Ab = sb + 1024 + s * STAGE;
        const uint32_t Bb = Ab + 16384;
        #pragma unroll
        for (int ks = 0; ks < 4; ks++) {
            uint32_t af[2][4];
            #pragma unroll
            for (int im = 0; im < 2; im++) {
                uint32_t addr = (Ab + (uint32_t)((wm * 32 + im * 16 + rl) * 128)
                                    + (uint32_t)(ks * 32) + khalf) ^ xorv;
                LDSM_X4(af[im][0], af[im][1], af[im][2], af[im][3], addr);
            }
            #pragma unroll
            for (int in_ = 0; in_ < 4; in_++) {
                uint32_t b0, b1, b2, b3;
                uint32_t addr = (Bb + (uint32_t)((wn * 64 + in_ * 16 + rl) * 128)
                                    + (uint32_t)(ks * 32) + khalf) ^ xorv;
                LDSM_X4(b0, b1, b2, b3, addr);
                #pragma unroll
                for (int im = 0; im < 2; im++) {
                    MMA16816(acc[im][2 * in_],     af[im], b0, b2);
                    MMA16816(acc[im][2 * in_ + 1], af[im], b1, b3);
                }
            }
        }
        BAR_ARRIVE(3 + s, NTHR);                      // signal stage empty
    }

    // -------- epilogue: + bias, relu, store --------
    const int g = lane >> 2;
    const int cpair = (lane & 3) * 2;
    #pragma unroll
    for (int im = 0; im < 2; im++) {
        int m0 = mblk * 128 + wm * 32 + im * 16 + g;
        #pragma unroll
        for (int j = 0; j < 8; j++) {
            int n = wn * 64 + j * 8 + cpair;
            float bv0 = bias_s[n], bv1 = bias_s[n + 1];
            float2 v0 = make_float2(fmaxf(acc[im][j][0] + bv0, 0.f),
                                    fmaxf(acc[im][j][1] + bv1, 0.f));
            float2 v1 = make_float2(fmaxf(acc[im][j][2] + bv0, 0.f),
                                    fmaxf(acc[im][j][3] + bv1, 0.f));
            *(float2*)(out + (size_t)m0 * 256 + n)       = v0;
            *(float2*)(out + (size_t)(m0 + 8) * 256 + n) = v1;
        }
    }
}

// ============================================================
// kernel_launch
// ============================================================
extern "C" void kernel_launch(void* const* d_in, const int* in_sizes, int n_in,
                              void* d_out, int out_size) {
    const float* text       = (const float*)d_in[0];
    const float* image      = (const float*)d_in[1];
    const float* W_text     = (const float*)d_in[2];
    const float* b_text     = (const float*)d_in[3];
    const float* W_img      = (const float*)d_in[4];
    const float* b_img      = (const float*)d_in[5];
    const float* in_proj_w  = (const float*)d_in[6];
    const float* in_proj_b  = (const float*)d_in[7];
    const float* out_proj_w = (const float*)d_in[8];
    const float* out_proj_b = (const float*)d_in[9];
    const float* W_fuse     = (const float*)d_in[10];
    const float* b_fuse     = (const float*)d_in[11];
    const int batch = in_sizes[0] / 512;

    // Precompute (3 launches, bias folded in):
    k_M1<<<dim3(4, 4, 2), 256>>>(out_proj_w, in_proj_w + 512 * 256,
                                 in_proj_b, out_proj_b);
    k_G <<<dim3(4, 4, 2), 256>>>(W_fuse);
    k_W <<<dim3(8, 4, 3), 256>>>(W_text, W_img, W_fuse, b_text, b_img, b_fuse);

    cudaFuncSetAttribute(fused_gemm, cudaFuncAttributeMaxDynamicSharedMemorySize, DYNSMEM);
    fused_gemm<<<batch / 128, NTHR, DYNSMEM>>>(text, image, (float*)d_out);
}

// round 8
// speedup vs baseline: 1.8876x; 1.8876x over previous
#include <cuda_runtime.h>
#include <cuda_fp16.h>
#include <cstdint>

// ============================================================
// Problem: out[B,256] = relu(X[B,1024] @ W^T + c)
//   X = [text | image], W/c precomputed from small weights.
//   B = 65536, H = 256, K = 1024.
// Reassociated precompute (depth 2):
//   X1 = Wf1@Wo, X2 = Wf2@Wo          [256x256]
//   Y_t = Wv@W_text, Y_i = Wv@W_img   [256x512]
//   W[:, :512] = X2@Y_t ; W[:, 512:] = X1@Y_i   (fp16)
//   b1 = Wo@bv + bo ; u_t = Wv@b_text ; u_i = Wv@b_img
//   c  = X1@u_i + X2@u_t + (Wf1+Wf2)@b1 + b_fuse
// ============================================================
#define HDIM 256
#define KTOT 1024

// ---------------- device scratch ----------------
__device__ float  g_X1[HDIM * HDIM];
__device__ float  g_X2[HDIM * HDIM];
__device__ float  g_Yt[HDIM * 512];
__device__ float  g_Yi[HDIM * 512];
__device__ __half g_W16[HDIM * KTOT];
__device__ float  g_b1[HDIM];
__device__ float  g_ut[HDIM];
__device__ float  g_ui[HDIM];
__device__ float  g_c[HDIM];

// ---------------- PTX helpers ----------------
__device__ __forceinline__ uint32_t smem_u32(const void* p) {
    uint32_t a;
    asm("{ .reg .u64 t; cvta.to.shared.u64 t, %1; cvt.u32.u64 %0, t; }"
        : "=r"(a) : "l"(p));
    return a;
}

#define SW(x) ((x) ^ (((x) >> 3) & 0x70))

#define LDSM_X4(r0, r1, r2, r3, addr) \
    asm volatile("ldmatrix.sync.aligned.m8n8.x4.shared.b16 {%0,%1,%2,%3}, [%4];\n" \
        : "=r"(r0), "=r"(r1), "=r"(r2), "=r"(r3) : "r"(addr))

#define MMA16816(d, a, b0_, b1_) \
    asm volatile("mma.sync.aligned.m16n8k16.row.col.f32.f16.f16.f32 " \
        "{%0,%1,%2,%3}, {%4,%5,%6,%7}, {%8,%9}, {%0,%1,%2,%3};\n" \
        : "+f"((d)[0]), "+f"((d)[1]), "+f"((d)[2]), "+f"((d)[3]) \
        : "r"((a)[0]), "r"((a)[1]), "r"((a)[2]), "r"((a)[3]), "r"(b0_), "r"(b1_))

#define CP_ASYNC16(dst, src) \
    asm volatile("cp.async.cg.shared.global [%0], [%1], 16;\n" :: "r"(dst), "l"(src))
#define CP_COMMIT() asm volatile("cp.async.commit_group;\n")
#define CP_WAIT0()  asm volatile("cp.async.wait_group 0;\n" ::: "memory")

// ============================================================
// Precompute: 32x32-tile fp32 GEMM, register-double-buffered
// ============================================================
template<bool HALF_OUT>
__device__ __forceinline__ void gemm32_body(const float* __restrict__ A, int lda,
                                            const float* __restrict__ B, int ldb,
                                            void* __restrict__ C, int ldc, int K,
                                            int i0, int j0) {
    __shared__ float As[32][34];   // As[k][m] (transposed)
    __shared__ float Bs[32][34];   // Bs[k][n]
    const int t = threadIdx.x;
    const int tx = t & 15, ty = t >> 4;
    float acc[2][2] = {};

    int rr[4], cc[4];
    #pragma unroll
    for (int u = 0; u < 4; u++) {
        int idx = t + u * 256;
        rr[u] = idx >> 5;  cc[u] = idx & 31;
    }
    float ra[4], rb[4];
    #pragma unroll
    for (int u = 0; u < 4; u++) {
        ra[u] = A[(size_t)(i0 + rr[u]) * lda + cc[u]];
        rb[u] = B[(size_t)rr[u] * ldb + j0 + cc[u]];
    }

    for (int k0 = 0; k0 < K; k0 += 32) {
        #pragma unroll
        for (int u = 0; u < 4; u++) {
            As[cc[u]][rr[u]] = ra[u];
            Bs[rr[u]][cc[u]] = rb[u];
        }
        __syncthreads();
        if (k0 + 32 < K) {
            #pragma unroll
            for (int u = 0; u < 4; u++) {
                ra[u] = A[(size_t)(i0 + rr[u]) * lda + k0 + 32 + cc[u]];
                rb[u] = B[(size_t)(k0 + 32 + rr[u]) * ldb + j0 + cc[u]];
            }
        }
        #pragma unroll
        for (int k = 0; k < 32; k++) {
            float2 a2 = *(const float2*)&As[k][ty * 2];
            float2 b2 = *(const float2*)&Bs[k][tx * 2];
            acc[0][0] += a2.x * b2.x; acc[0][1] += a2.x * b2.y;
            acc[1][0] += a2.y * b2.x; acc[1][1] += a2.y * b2.y;
        }
        __syncthreads();
    }
    #pragma unroll
    for (int r = 0; r < 2; r++)
        #pragma unroll
        for (int c = 0; c < 2; c++) {
            size_t o = (size_t)(i0 + ty * 2 + r) * ldc + j0 + tx * 2 + c;
            if (HALF_OUT) ((__half*)C)[o] = __float2half_rn(acc[r][c]);
            else          ((float*)C)[o]  = acc[r][c];
        }
}

__device__ __forceinline__ float dot256(const float* __restrict__ a,
                                        const float* __restrict__ b) {
    const float4* a4 = (const float4*)a;
    const float4* b4 = (const float4*)b;
    float s = 0.f;
    #pragma unroll 8
    for (int k = 0; k < 64; k++) {
        float4 x = __ldg(&a4[k]), y = __ldg(&b4[k]);
        s += x.x * y.x + x.y * y.y + x.z * y.z + x.w * y.w;
    }
    return s;
}

// Launch 1: everything that depends only on inputs.
//  z=0: x<8 -> X1 = Wf1@Wo ; (x,y)=(8,0) b1 ; (9,0) u_t ; (10,0) u_i
//  z=1: x<8 -> X2 = Wf2@Wo
//  z=2: Y_t = Wv@W_text   z=3: Y_i = Wv@W_img
__global__ void k_pre1(const float* __restrict__ Wo, const float* __restrict__ Wv,
                       const float* __restrict__ W_fuse,
                       const float* __restrict__ W_text, const float* __restrict__ W_img,
                       const float* __restrict__ in_proj_b,
                       const float* __restrict__ out_proj_b,
                       const float* __restrict__ b_text, const float* __restrict__ b_img) {
    const int z = blockIdx.z;
    if (z == 0) {
        if (blockIdx.x < 8) {
            gemm32_body<false>(W_fuse, 512, Wo, 256, g_X1, 256, 256,
                               blockIdx.y * 32, blockIdx.x * 32);
        } else if (blockIdx.y == 0) {
            const int i = threadIdx.x;
            if (blockIdx.x == 8)
                g_b1[i] = dot256(Wo + i * HDIM, in_proj_b + 2 * HDIM) + out_proj_b[i];
            else if (blockIdx.x == 9)
                g_ut[i] = dot256(Wv + i * HDIM, b_text);
            else if (blockIdx.x == 10)
                g_ui[i] = dot256(Wv + i * HDIM, b_img);
        }
        return;
    }
    if (z == 1) {
        if (blockIdx.x < 8)
            gemm32_body<false>(W_fuse + 256, 512, Wo, 256, g_X2, 256, 256,
                               blockIdx.y * 32, blockIdx.x * 32);
        return;
    }
    if (z == 2) {
        gemm32_body<false>(Wv, 256, W_text, 512, g_Yt, 512, 256,
                           blockIdx.y * 32, blockIdx.x * 32);
        return;
    }
    gemm32_body<false>(Wv, 256, W_img, 512, g_Yi, 512, 256,
                       blockIdx.y * 32, blockIdx.x * 32);
}

// Launch 2:
//  z=0: W[:, :512]  = X2@Y_t (fp16)    z=1: W[:, 512:] = X1@Y_i (fp16)
//  z=2 (0,0): c = X1@u_i + X2@u_t + (Wf1+Wf2)@b1 + b_fuse
__global__ void k_pre2(const float* __restrict__ W_fuse,
                       const float* __restrict__ b_fuse) {
    const int z = blockIdx.z;
    if (z == 0) {
        gemm32_body<true>(g_X2, 256, g_Yt, 512, g_W16, 1024, 256,
                          blockIdx.y * 32, blockIdx.x * 32);
        return;
    }
    if (z == 1) {
        gemm32_body<true>(g_X1, 256, g_Yi, 512, g_W16 + 512, 1024, 256,
                          blockIdx.y * 32, blockIdx.x * 32);
        return;
    }
    if (blockIdx.x | blockIdx.y) return;
    const int i = threadIdx.x;
    float s = b_fuse[i] + dot256(g_X1 + i * HDIM, g_ui) + dot256(g_X2 + i * HDIM, g_ut);
    const float4* w1 = (const float4*)(W_fuse + i * 512);
    const float4* w2 = (const float4*)(W_fuse + i * 512 + 256);
    const float4* v1 = (const float4*)g_b1;
    #pragma unroll 8
    for (int k = 0; k < 64; k++) {
        float4 c1 = __ldg(&w1[k]), c2 = __ldg(&w2[k]), b = v1[k];
        s += (c1.x + c2.x) * b.x + (c1.y + c2.y) * b.y
           + (c1.z + c2.z) * b.z + (c1.w + c2.w) * b.w;
    }
    g_c[i] = s;
}

// ============================================================
// Main GEMM: CTA tile 64x256, 256 threads (8 warps, warp 32x64),
// K-chunk 64, double-buffered, round-6-style inner loop,
// 2 CTAs/SM for decoupled barriers.
// ============================================================
#define STAGE 40960                    // 8KB A + 32KB B
#define DYNSMEM (1024 + 1024 + 2 * STAGE)

__global__ void __launch_bounds__(256, 2)
fused_gemm(const float* __restrict__ text, const float* __restrict__ image,
           float* __restrict__ out) {
    extern __shared__ char smem_raw[];
    char* dsm = (char*)(((uintptr_t)smem_raw + 1023) & ~(uintptr_t)1023);
    const uint32_t sb = smem_u32(dsm);
    const int tid = threadIdx.x;
    const int lane = tid & 31;
    const int wid = tid >> 5;          // 0..7
    const int wm = wid & 1;            // 2 m-blocks of 32
    const int wn = wid >> 1;           // 4 n-blocks of 64
    const int mblk = blockIdx.x;

    float* bias_s = (float*)dsm;
    bias_s[tid] = g_c[tid];

    const float* srcT = text  + (size_t)mblk * 64 * 512;
    const float* srcI = image + (size_t)mblk * 64 * 512;

    const int a_c4 = tid & 15, a_r0 = tid >> 4;   // A: rows a_r0 + u*16, u<4
    const int b_c16 = tid & 7, b_r0 = tid >> 3;   // B: rows b_r0 + u*32, u<8

    // -------- prologue: chunk 0 --------
    float4 fa[4];
    #pragma unroll
    for (int u = 0; u < 4; u++)
        fa[u] = __ldg((const float4*)(srcT + (size_t)(a_r0 + u * 16) * 512 + a_c4 * 4));
    {
        uint32_t Bb = sb + 1024 + 8192;
        #pragma unroll
        for (int u = 0; u < 8; u++) {
            int r = b_r0 + u * 32;
            uint32_t dst = Bb + SW((uint32_t)(r * 128 + b_c16 * 16));
            CP_ASYNC16(dst, g_W16 + (size_t)r * 1024 + b_c16 * 8);
        }
        CP_COMMIT();
    }
    {
        char* Ab = dsm + 1024;
        #pragma unroll
        for (int u = 0; u < 4; u++) {
            int r = a_r0 + u * 16;
            uint32_t off = SW((uint32_t)(r * 128 + a_c4 * 8));
            __half2 h0 = __floats2half2_rn(fa[u].x, fa[u].y);
            __half2 h1 = __floats2half2_rn(fa[u].z, fa[u].w);
            *(uint2*)(Ab + off) = make_uint2(*(uint32_t*)&h0, *(uint32_t*)&h1);
        }
    }
    CP_WAIT0();
    __syncthreads();

    float acc[2][8][4] = {};

    const uint32_t xorv  = (uint32_t)((lane & 7) << 4);
    const int      rl    = lane & 15;
    const uint32_t khalf = (uint32_t)(((lane >> 4) & 1) * 16);

    #pragma unroll 1
    for (int kc = 0; kc < 16; kc++) {
        const int cur = kc & 1;
        const int nxt = cur ^ 1;

        // ---- prefetch next chunk: A -> regs, B -> cp.async ----
        if (kc < 15) {
            const int kn = kc + 1;
            const float* src = (kn < 8) ? srcT : srcI;
            const int kl = (kn & 7) * 64;
            #pragma unroll
            for (int u = 0; u < 4; u++)
                fa[u] = __ldg((const float4*)(src + (size_t)(a_r0 + u * 16) * 512 + kl + a_c4 * 4));
            uint32_t Bb = sb + 1024 + nxt * STAGE + 8192;
            #pragma unroll
            for (int u = 0; u < 8; u++) {
                int r = b_r0 + u * 32;
                uint32_t dst = Bb + SW((uint32_t)(r * 128 + b_c16 * 16));
                CP_ASYNC16(dst, g_W16 + (size_t)r * 1024 + kn * 64 + b_c16 * 8);
            }
            CP_COMMIT();
        }

        // ---- compute on cur ----
        const uint32_t Ab = sb + 1024 + cur * STAGE;
        const uint32_t Bb = Ab + 8192;
        #pragma unroll
        for (int ks = 0; ks < 4; ks++) {
            uint32_t af[2][4];
            #pragma unroll
            for (int im = 0; im < 2; im++) {
                uint32_t addr = (Ab + (uint32_t)((wm * 32 + im * 16 + rl) * 128)
                                    + (uint32_t)(ks * 32) + khalf) ^ xorv;
                LDSM_X4(af[im][0], af[im][1], af[im][2], af[im][3], addr);
            }
            #pragma unroll
            for (int in_ = 0; in_ < 4; in_++) {
                uint32_t b0, b1, b2, b3;
                uint32_t addr = (Bb + (uint32_t)((wn * 64 + in_ * 16 + rl) * 128)
                                    + (uint32_t)(ks * 32) + khalf) ^ xorv;
                LDSM_X4(b0, b1, b2, b3, addr);
                #pragma unroll
                for (int im = 0; im < 2; im++) {
                    MMA16816(acc[im][2 * in_],     af[im], b0, b2);
                    MMA16816(acc[im][2 * in_ + 1], af[im], b1, b3);
                }
            }
        }

        // ---- stage A-next into smem, then close the stage ----
        if (kc < 15) {
            char* Abn = dsm + 1024 + nxt * STAGE;
            #pragma unroll
            for (int u = 0; u < 4; u++) {
                int r = a_r0 + u * 16;
                uint32_t off = SW((uint32_t)(r * 128 + a_c4 * 8));
                __half2 h0 = __floats2half2_rn(fa[u].x, fa[u].y);
                __half2 h1 = __floats2half2_rn(fa[u].z, fa[u].w);
                *(uint2*)(Abn + off) = make_uint2(*(uint32_t*)&h0, *(uint32_t*)&h1);
            }
            CP_WAIT0();
        }
        __syncthreads();
    }

    // -------- epilogue: + bias, relu, store --------
    const int g = lane >> 2;
    const int cpair = (lane & 3) * 2;
    #pragma unroll
    for (int im = 0; im < 2; im++) {
        int m0 = mblk * 64 + wm * 32 + im * 16 + g;
        #pragma unroll
        for (int j = 0; j < 8; j++) {
            int n = wn * 64 + j * 8 + cpair;
            float bv0 = bias_s[n], bv1 = bias_s[n + 1];
            float2 v0 = make_float2(fmaxf(acc[im][j][0] + bv0, 0.f),
                                    fmaxf(acc[im][j][1] + bv1, 0.f));
            float2 v1 = make_float2(fmaxf(acc[im][j][2] + bv0, 0.f),
                                    fmaxf(acc[im][j][3] + bv1, 0.f));
            *(float2*)(out + (size_t)m0 * 256 + n)       = v0;
            *(float2*)(out + (size_t)(m0 + 8) * 256 + n) = v1;
        }
    }
}

// ============================================================
// kernel_launch
// ============================================================
extern "C" void kernel_launch(void* const* d_in, const int* in_sizes, int n_in,
                              void* d_out, int out_size) {
    const float* text       = (const float*)d_in[0];
    const float* image      = (const float*)d_in[1];
    const float* W_text     = (const float*)d_in[2];
    const float* b_text     = (const float*)d_in[3];
    const float* W_img      = (const float*)d_in[4];
    const float* b_img      = (const float*)d_in[5];
    const float* in_proj_w  = (const float*)d_in[6];
    const float* in_proj_b  = (const float*)d_in[7];
    const float* out_proj_w = (const float*)d_in[8];
    const float* out_proj_b = (const float*)d_in[9];
    const float* W_fuse     = (const float*)d_in[10];
    const float* b_fuse     = (const float*)d_in[11];
    const int batch = in_sizes[0] / 512;

    // Precompute: 2 launches, depth-2 reassociated chain.
    k_pre1<<<dim3(16, 8, 4), 256>>>(out_proj_w, in_proj_w + 512 * 256, W_fuse,
                                    W_text, W_img, in_proj_b, out_proj_b,
                                    b_text, b_img);
    k_pre2<<<dim3(16, 8, 3), 256>>>(W_fuse, b_fuse);

    cudaFuncSetAttribute(fused_gemm, cudaFuncAttributeMaxDynamicSharedMemorySize, DYNSMEM);
    fused_gemm<<<batch / 64, 256, DYNSMEM>>>(text, image, (float*)d_out);
}

// round 9
// speedup vs baseline: 2.0306x; 1.0758x over previous
#include <cuda_runtime.h>
#include <cuda_fp16.h>
#include <cstdint>

// ============================================================
// Problem: out[B,256] = relu(X[B,1024] @ W^T + c)
//   X = [text | image], W/c precomputed from small weights.
//   B = 65536, H = 256, K = 1024.
// Reassociated precompute (depth 2):
//   X1 = Wf1@Wo, X2 = Wf2@Wo          [256x256]
//   Y_t = Wv@W_text, Y_i = Wv@W_img   [256x512]
//   W[:, :512] = X2@Y_t ; W[:, 512:] = X1@Y_i   (fp16)
//   b1 = Wo@bv + bo ; u_t = Wv@b_text ; u_i = Wv@b_img
//   c  = X1@u_i + X2@u_t + (Wf1+Wf2)@b1 + b_fuse
// ============================================================
#define HDIM 256
#define KTOT 1024

// ---------------- device scratch ----------------
__device__ float  g_X1[HDIM * HDIM];
__device__ float  g_X2[HDIM * HDIM];
__device__ float  g_Yt[HDIM * 512];
__device__ float  g_Yi[HDIM * 512];
__device__ __half g_W16[HDIM * KTOT];
__device__ float  g_b1[HDIM];
__device__ float  g_ut[HDIM];
__device__ float  g_ui[HDIM];
__device__ float  g_c[HDIM];

// ---------------- PTX helpers ----------------
__device__ __forceinline__ uint32_t smem_u32(const void* p) {
    uint32_t a;
    asm("{ .reg .u64 t; cvta.to.shared.u64 t, %1; cvt.u32.u64 %0, t; }"
        : "=r"(a) : "l"(p));
    return a;
}

#define SW(x) ((x) ^ (((x) >> 3) & 0x70))

#define LDSM_X4(r0, r1, r2, r3, addr) \
    asm volatile("ldmatrix.sync.aligned.m8n8.x4.shared.b16 {%0,%1,%2,%3}, [%4];\n" \
        : "=r"(r0), "=r"(r1), "=r"(r2), "=r"(r3) : "r"(addr))

#define MMA16816(d, a, b0_, b1_) \
    asm volatile("mma.sync.aligned.m16n8k16.row.col.f32.f16.f16.f32 " \
        "{%0,%1,%2,%3}, {%4,%5,%6,%7}, {%8,%9}, {%0,%1,%2,%3};\n" \
        : "+f"((d)[0]), "+f"((d)[1]), "+f"((d)[2]), "+f"((d)[3]) \
        : "r"((a)[0]), "r"((a)[1]), "r"((a)[2]), "r"((a)[3]), "r"(b0_), "r"(b1_))

#define CP_ASYNC16(dst, src) \
    asm volatile("cp.async.cg.shared.global [%0], [%1], 16;\n" :: "r"(dst), "l"(src))
#define CP_COMMIT() asm volatile("cp.async.commit_group;\n")
#define CP_WAIT0()  asm volatile("cp.async.wait_group 0;\n" ::: "memory")

// ============================================================
// Precompute: 64x64-tile fp32 GEMM, 4x4/thread, reg-double-buffered
// ============================================================
template<bool HALF_OUT>
__device__ __forceinline__ void gemm64_body(const float* __restrict__ A, int lda,
                                            const float* __restrict__ B, int ldb,
                                            void* __restrict__ C, int ldc, int K,
                                            int i0, int j0) {
    __shared__ float As[32][72];   // As[k][m] (transposed)
    __shared__ float Bs[32][72];   // Bs[k][n]
    const int t = threadIdx.x;
    const int tx = t & 15, ty = t >> 4;
    float acc[4][4] = {};

    int ar[8], ac[8], br[8], bc[8];
    #pragma unroll
    for (int u = 0; u < 8; u++) {
        int idx = t + u * 256;
        ar[u] = idx >> 5;  ac[u] = idx & 31;   // A: 64 rows x 32 k
        br[u] = idx >> 6;  bc[u] = idx & 63;   // B: 32 k x 64 cols
    }
    float ra[8], rb[8];
    #pragma unroll
    for (int u = 0; u < 8; u++) {
        ra[u] = A[(size_t)(i0 + ar[u]) * lda + ac[u]];
        rb[u] = B[(size_t)br[u] * ldb + j0 + bc[u]];
    }

    for (int k0 = 0; k0 < K; k0 += 32) {
        #pragma unroll
        for (int u = 0; u < 8; u++) {
            As[ac[u]][ar[u]] = ra[u];
            Bs[br[u]][bc[u]] = rb[u];
        }
        __syncthreads();
        if (k0 + 32 < K) {
            #pragma unroll
            for (int u = 0; u < 8; u++) {
                ra[u] = A[(size_t)(i0 + ar[u]) * lda + k0 + 32 + ac[u]];
                rb[u] = B[(size_t)(k0 + 32 + br[u]) * ldb + j0 + bc[u]];
            }
        }
        #pragma unroll
        for (int k = 0; k < 32; k++) {
            float4 a4 = *(const float4*)&As[k][ty * 4];
            float4 b4 = *(const float4*)&Bs[k][tx * 4];
            acc[0][0] += a4.x * b4.x; acc[0][1] += a4.x * b4.y;
            acc[0][2] += a4.x * b4.z; acc[0][3] += a4.x * b4.w;
            acc[1][0] += a4.y * b4.x; acc[1][1] += a4.y * b4.y;
            acc[1][2] += a4.y * b4.z; acc[1][3] += a4.y * b4.w;
            acc[2][0] += a4.z * b4.x; acc[2][1] += a4.z * b4.y;
            acc[2][2] += a4.z * b4.z; acc[2][3] += a4.z * b4.w;
            acc[3][0] += a4.w * b4.x; acc[3][1] += a4.w * b4.y;
            acc[3][2] += a4.w * b4.z; acc[3][3] += a4.w * b4.w;
        }
        __syncthreads();
    }
    #pragma unroll
    for (int r = 0; r < 4; r++)
        #pragma unroll
        for (int c = 0; c < 4; c++) {
            size_t o = (size_t)(i0 + ty * 4 + r) * ldc + j0 + tx * 4 + c;
            if (HALF_OUT) ((__half*)C)[o] = __float2half_rn(acc[r][c]);
            else          ((float*)C)[o]  = acc[r][c];
        }
}

__device__ __forceinline__ float dot256(const float* __restrict__ a,
                                        const float* __restrict__ b) {
    const float4* a4 = (const float4*)a;
    const float4* b4 = (const float4*)b;
    float s = 0.f;
    #pragma unroll 8
    for (int k = 0; k < 64; k++) {
        float4 x = __ldg(&a4[k]), y = __ldg(&b4[k]);
        s += x.x * y.x + x.y * y.y + x.z * y.z + x.w * y.w;
    }
    return s;
}

// Launch 1 (input-only work), grid (8,4,4):
//  z=0: x<4 -> X1 = Wf1@Wo ; (x,y)=(4..6, 0) -> b1, u_t, u_i
//  z=1: x<4 -> X2 = Wf2@Wo
//  z=2: Y_t = Wv@W_text   z=3: Y_i = Wv@W_img
__global__ void k_pre1(const float* __restrict__ Wo, const float* __restrict__ Wv,
                       const float* __restrict__ W_fuse,
                       const float* __restrict__ W_text, const float* __restrict__ W_img,
                       const float* __restrict__ in_proj_b,
                       const float* __restrict__ out_proj_b,
                       const float* __restrict__ b_text, const float* __restrict__ b_img) {
    const int z = blockIdx.z;
    if (z == 0) {
        if (blockIdx.x < 4) {
            gemm64_body<false>(W_fuse, 512, Wo, 256, g_X1, 256, 256,
                               blockIdx.y * 64, blockIdx.x * 64);
        } else if (blockIdx.y == 0) {
            const int i = threadIdx.x;
            if (blockIdx.x == 4)
                g_b1[i] = dot256(Wo + i * HDIM, in_proj_b + 2 * HDIM) + out_proj_b[i];
            else if (blockIdx.x == 5)
                g_ut[i] = dot256(Wv + i * HDIM, b_text);
            else if (blockIdx.x == 6)
                g_ui[i] = dot256(Wv + i * HDIM, b_img);
        }
        return;
    }
    if (z == 1) {
        if (blockIdx.x < 4)
            gemm64_body<false>(W_fuse + 256, 512, Wo, 256, g_X2, 256, 256,
                               blockIdx.y * 64, blockIdx.x * 64);
        return;
    }
    if (z == 2) {
        gemm64_body<false>(Wv, 256, W_text, 512, g_Yt, 512, 256,
                           blockIdx.y * 64, blockIdx.x * 64);
        return;
    }
    gemm64_body<false>(Wv, 256, W_img, 512, g_Yi, 512, 256,
                       blockIdx.y * 64, blockIdx.x * 64);
}

// Launch 2, grid (8,4,3):
//  z=0: W[:, :512] = X2@Y_t (fp16)   z=1: W[:, 512:] = X1@Y_i (fp16)
//  z=2 (0,0): c = X1@u_i + X2@u_t + (Wf1+Wf2)@b1 + b_fuse
__global__ void k_pre2(const float* __restrict__ W_fuse,
                       const float* __restrict__ b_fuse) {
    const int z = blockIdx.z;
    if (z == 0) {
        gemm64_body<true>(g_X2, 256, g_Yt, 512, g_W16, 1024, 256,
                          blockIdx.y * 64, blockIdx.x * 64);
        return;
    }
    if (z == 1) {
        gemm64_body<true>(g_X1, 256, g_Yi, 512, g_W16 + 512, 1024, 256,
                          blockIdx.y * 64, blockIdx.x * 64);
        return;
    }
    if (blockIdx.x | blockIdx.y) return;
    const int i = threadIdx.x;
    float s = b_fuse[i] + dot256(g_X1 + i * HDIM, g_ui) + dot256(g_X2 + i * HDIM, g_ut);
    const float4* w1 = (const float4*)(W_fuse + i * 512);
    const float4* w2 = (const float4*)(W_fuse + i * 512 + 256);
    const float4* v1 = (const float4*)g_b1;
    #pragma unroll 8
    for (int k = 0; k < 64; k++) {
        float4 c1 = __ldg(&w1[k]), c2 = __ldg(&w2[k]), b = v1[k];
        s += (c1.x + c2.x) * b.x + (c1.y + c2.y) * b.y
           + (c1.z + c2.z) * b.z + (c1.w + c2.w) * b.w;
    }
    g_c[i] = s;
}

// ============================================================
// Main GEMM: CTA tile 64x256, 256 threads (8 warps, warp 32x64),
// K-chunk 64, double-buffered smem, 2 CTAs/SM,
// constant-index fragment pipelining (1 B-group + 1 A-ks ahead).
// ============================================================
#define STAGE 40960                    // 8KB A + 32KB B
#define DYNSMEM (1024 + 1024 + 2 * STAGE)

__global__ void __launch_bounds__(256, 2)
fused_gemm(const float* __restrict__ text, const float* __restrict__ image,
           float* __restrict__ out) {
    extern __shared__ char smem_raw[];
    char* dsm = (char*)(((uintptr_t)smem_raw + 1023) & ~(uintptr_t)1023);
    const uint32_t sb = smem_u32(dsm);
    const int tid = threadIdx.x;
    const int lane = tid & 31;
    const int wid = tid >> 5;          // 0..7
    const int wm = wid & 1;            // 2 m-blocks of 32
    const int wn = wid >> 1;           // 4 n-blocks of 64
    const int mblk = blockIdx.x;

    float* bias_s = (float*)dsm;
    bias_s[tid] = g_c[tid];

    const float* srcT = text  + (size_t)mblk * 64 * 512;
    const float* srcI = image + (size_t)mblk * 64 * 512;

    const int a_c4 = tid & 15, a_r0 = tid >> 4;   // A: rows a_r0 + u*16, u<4
    const int b_c16 = tid & 7, b_r0 = tid >> 3;   // B: rows b_r0 + u*32, u<8

    // -------- prologue: chunk 0 --------
    float4 fa[4];
    #pragma unroll
    for (int u = 0; u < 4; u++)
        fa[u] = __ldg((const float4*)(srcT + (size_t)(a_r0 + u * 16) * 512 + a_c4 * 4));
    {
        uint32_t Bb = sb + 1024 + 8192;
        #pragma unroll
        for (int u = 0; u < 8; u++) {
            int r = b_r0 + u * 32;
            uint32_t dst = Bb + SW((uint32_t)(r * 128 + b_c16 * 16));
            CP_ASYNC16(dst, g_W16 + (size_t)r * 1024 + b_c16 * 8);
        }
        CP_COMMIT();
    }
    {
        char* Ab = dsm + 1024;
        #pragma unroll
        for (int u = 0; u < 4; u++) {
            int r = a_r0 + u * 16;
            uint32_t off = SW((uint32_t)(r * 128 + a_c4 * 8));
            __half2 h0 = __floats2half2_rn(fa[u].x, fa[u].y);
            __half2 h1 = __floats2half2_rn(fa[u].z, fa[u].w);
            *(uint2*)(Ab + off) = make_uint2(*(uint32_t*)&h0, *(uint32_t*)&h1);
        }
    }
    CP_WAIT0();
    __syncthreads();

    float acc[2][8][4] = {};

    const uint32_t xorv  = (uint32_t)((lane & 7) << 4);
    const int      rl    = lane & 15;
    const uint32_t khalf = (uint32_t)(((lane >> 4) & 1) * 16);

    #pragma unroll 1
    for (int kc = 0; kc < 16; kc++) {
        const int cur = kc & 1;
        const int nxt = cur ^ 1;

        // ---- prefetch next chunk: A -> regs, B -> cp.async ----
        if (kc < 15) {
            const int kn = kc + 1;
            const float* src = (kn < 8) ? srcT : srcI;
            const int kl = (kn & 7) * 64;
            #pragma unroll
            for (int u = 0; u < 4; u++)
                fa[u] = __ldg((const float4*)(src + (size_t)(a_r0 + u * 16) * 512 + kl + a_c4 * 4));
            uint32_t Bb = sb + 1024 + nxt * STAGE + 8192;
            #pragma unroll
            for (int u = 0; u < 8; u++) {
                int r = b_r0 + u * 32;
                uint32_t dst = Bb + SW((uint32_t)(r * 128 + b_c16 * 16));
                CP_ASYNC16(dst, g_W16 + (size_t)r * 1024 + kn * 64 + b_c16 * 8);
            }
            CP_COMMIT();
        }

        // ---- compute on cur, fragment-pipelined ----
        const uint32_t Ab = sb + 1024 + cur * STAGE;
        const uint32_t Bb = Ab + 8192;
        uint32_t af[2][2][4];   // [ks&1][im][reg]
        uint32_t bf[2][4];      // [group&1][reg]

        // preload ks=0: A frags (both im) + B group 0
        #pragma unroll
        for (int im = 0; im < 2; im++) {
            uint32_t addr = (Ab + (uint32_t)((wm * 32 + im * 16 + rl) * 128) + khalf) ^ xorv;
            LDSM_X4(af[0][im][0], af[0][im][1], af[0][im][2], af[0][im][3], addr);
        }
        {
            uint32_t addr = (Bb + (uint32_t)((wn * 64 + rl) * 128) + khalf) ^ xorv;
            LDSM_X4(bf[0][0], bf[0][1], bf[0][2], bf[0][3], addr);
        }

        #pragma unroll
        for (int ks = 0; ks < 4; ks++) {
            const int cb = ks & 1;
            #pragma unroll
            for (int in_ = 0; in_ < 4; in_++) {
                const int bc = in_ & 1, bn = bc ^ 1;
                if (in_ < 3) {
                    // prefetch next B group within this ks
                    uint32_t addr = (Bb + (uint32_t)((wn * 64 + (in_ + 1) * 16 + rl) * 128)
                                        + (uint32_t)(ks * 32) + khalf) ^ xorv;
                    LDSM_X4(bf[bn][0], bf[bn][1], bf[bn][2], bf[bn][3], addr);
                } else if (ks < 3) {
                    // prefetch next ks: A frags + B group 0
                    #pragma unroll
                    for (int im = 0; im < 2; im++) {
                        uint32_t addr = (Ab + (uint32_t)((wm * 32 + im * 16 + rl) * 128)
                                            + (uint32_t)((ks + 1) * 32) + khalf) ^ xorv;
                        LDSM_X4(af[cb ^ 1][im][0], af[cb ^ 1][im][1],
                                af[cb ^ 1][im][2], af[cb ^ 1][im][3], addr);
                    }
                    uint32_t addr = (Bb + (uint32_t)((wn * 64 + rl) * 128)
                                        + (uint32_t)((ks + 1) * 32) + khalf) ^ xorv;
                    LDSM_X4(bf[bn][0], bf[bn][1], bf[bn][2], bf[bn][3], addr);
                }
                #pragma unroll
                for (int im = 0; im < 2; im++) {
                    MMA16816(acc[im][2 * in_],     af[cb][im], bf[bc][0], bf[bc][2]);
                    MMA16816(acc[im][2 * in_ + 1], af[cb][im], bf[bc][1], bf[bc][3]);
                }
            }
        }

        // ---- stage A-next into smem, then close the stage ----
        if (kc < 15) {
            char* Abn = dsm + 1024 + nxt * STAGE;
            #pragma unroll
            for (int u = 0; u < 4; u++) {
                int r = a_r0 + u * 16;
                uint32_t off = SW((uint32_t)(r * 128 + a_c4 * 8));
                __half2 h0 = __floats2half2_rn(fa[u].x, fa[u].y);
                __half2 h1 = __floats2half2_rn(fa[u].z, fa[u].w);
                *(uint2*)(Abn + off) = make_uint2(*(uint32_t*)&h0, *(uint32_t*)&h1);
            }
            CP_WAIT0();
        }
        __syncthreads();
    }

    // -------- epilogue: + bias, relu, store --------
    const int g = lane >> 2;
    const int cpair = (lane & 3) * 2;
    #pragma unroll
    for (int im = 0; im < 2; im++) {
        int m0 = mblk * 64 + wm * 32 + im * 16 + g;
        #pragma unroll
        for (int j = 0; j < 8; j++) {
            int n = wn * 64 + j * 8 + cpair;
            float bv0 = bias_s[n], bv1 = bias_s[n + 1];
            float2 v0 = make_float2(fmaxf(acc[im][j][0] + bv0, 0.f),
                                    fmaxf(acc[im][j][1] + bv1, 0.f));
            float2 v1 = make_float2(fmaxf(acc[im][j][2] + bv0, 0.f),
                                    fmaxf(acc[im][j][3] + bv1, 0.f));
            *(float2*)(out + (size_t)m0 * 256 + n)       = v0;
            *(float2*)(out + (size_t)(m0 + 8) * 256 + n) = v1;
        }
    }
}

// ============================================================
// kernel_launch
// ============================================================
extern "C" void kernel_launch(void* const* d_in, const int* in_sizes, int n_in,
                              void* d_out, int out_size) {
    const float* text       = (const float*)d_in[0];
    const float* image      = (const float*)d_in[1];
    const float* W_text     = (const float*)d_in[2];
    const float* b_text     = (const float*)d_in[3];
    const float* W_img      = (const float*)d_in[4];
    const float* b_img      = (const float*)d_in[5];
    const float* in_proj_w  = (const float*)d_in[6];
    const float* in_proj_b  = (const float*)d_in[7];
    const float* out_proj_w = (const float*)d_in[8];
    const float* out_proj_b = (const float*)d_in[9];
    const float* W_fuse     = (const float*)d_in[10];
    const float* b_fuse     = (const float*)d_in[11];
    const int batch = in_sizes[0] / 512;

    // Precompute: 2 launches, depth-2 reassociated chain.
    k_pre1<<<dim3(8, 4, 4), 256>>>(out_proj_w, in_proj_w + 512 * 256, W_fuse,
                                   W_text, W_img, in_proj_b, out_proj_b,
                                   b_text, b_img);
    k_pre2<<<dim3(8, 4, 3), 256>>>(W_fuse, b_fuse);

    cudaFuncSetAttribute(fused_gemm, cudaFuncAttributeMaxDynamicSharedMemorySize, DYNSMEM);
    fused_gemm<<<batch / 64, 256, DYNSMEM>>>(text, image, (float*)d_out);
}